// round 14
// baseline (speedup 1.0000x reference)
#include <cuda_runtime.h>

// Problem constants
#define NB 16
#define NT 256
#define NK 128
#define ND 256   // D_E == D_K == 256
#define NU 128

// Scratch (allocation-free rule: __device__ globals)
// Et duplicated (v,v) so score-phase FFMA2 needs no packing movs.
__device__ float2 g_Et2[NB * NT * NU];   // [b*NT+t][u] : (exp(2e), exp(2e))
__device__ float  g_EkT[NB * NU * NK];   // [b][u][k]   : exp(2kp), transposed

// exp(clamp(2x)) — tanh(a+b) factorization: tanh = 1 - 2/(1 + e^{2a}e^{2b})
__device__ __forceinline__ float eclamp(float x) {
    return __expf(fminf(fmaxf(2.0f * x, -16.0f), 16.0f));
}

// Packed f32x2 ops (sm_100+)
__device__ __forceinline__ unsigned long long fma2(unsigned long long a,
                                                   unsigned long long b,
                                                   unsigned long long c) {
    unsigned long long d;
    asm("fma.rn.f32x2 %0, %1, %2, %3;" : "=l"(d) : "l"(a), "l"(b), "l"(c));
    return d;
}
__device__ __forceinline__ unsigned long long mul2(unsigned long long a,
                                                   unsigned long long b) {
    unsigned long long d;
    asm("mul.rn.f32x2 %0, %1, %2;" : "=l"(d) : "l"(a), "l"(b));
    return d;
}
// packed reciprocal: 2x rcp.approx
__device__ __forceinline__ unsigned long long rcp2(unsigned long long v) {
    unsigned long long r;
    asm("{\n\t"
        ".reg .f32 lo, hi, rl, rh;\n\t"
        "mov.b64 {lo, hi}, %1;\n\t"
        "rcp.approx.f32 rl, lo;\n\t"
        "rcp.approx.f32 rh, hi;\n\t"
        "mov.b64 %0, {rl, rh};\n\t"
        "}" : "=l"(r) : "l"(v));
    return r;
}
__device__ __forceinline__ float2 u2f(unsigned long long v) {
    float2 r;
    asm("mov.b64 {%0, %1}, %2;" : "=f"(r.x), "=f"(r.y) : "l"(v));
    return r;
}

#define ONE2 0x3F8000003F800000ull   // packed (1.0f, 1.0f)

// ---------------------------------------------------------------------------
// Projection kernel (unchanged, proven):
//   blocks [0,256):   Et = exp(2*(enc@W1+b1))  -> g_Et2 duplicated
//   blocks [256,384): Ek = exp(2*(knw@W2+b2))  -> g_EkT transposed
// ---------------------------------------------------------------------------
__global__ __launch_bounds__(256) void proj_kernel(
    const float* __restrict__ enc, const float* __restrict__ knw,
    const float* __restrict__ W1, const float* __restrict__ b1,
    const float* __restrict__ W2, const float* __restrict__ b2)
{
    const int blk = blockIdx.x;
    const bool isE = (blk < 256);
    const float* __restrict__ A    = isE ? enc : knw;
    const float* __restrict__ W    = isE ? W1  : W2;
    const float* __restrict__ bias = isE ? b1  : b2;
    const int row0 = (isE ? blk : (blk - 256)) * 16;

    __shared__ float As[16][32];
    __shared__ float Bs[32][128];

    const int tid = threadIdx.x;
    const int tx  = tid & 31;
    const int ty  = tid >> 5;

    float4 acc0 = make_float4(0.f, 0.f, 0.f, 0.f);
    float4 acc1 = make_float4(0.f, 0.f, 0.f, 0.f);

    for (int kc = 0; kc < ND; kc += 32) {
        if (tid < 128) {
            int r  = tid >> 3;
            int c4 = tid & 7;
            float4 a = *(const float4*)&A[(row0 + r) * ND + kc + c4 * 4];
            *(float4*)&As[r][c4 * 4] = a;
        }
        #pragma unroll
        for (int i = 0; i < 4; i++) {
            int lin = tid + i * 256;
            int r   = lin >> 5;
            int c4  = lin & 31;
            *(float4*)&Bs[r][c4 * 4] = *(const float4*)&W[(kc + r) * NU + c4 * 4];
        }
        __syncthreads();

        #pragma unroll
        for (int kk = 0; kk < 32; kk++) {
            float4 bv = *(float4*)&Bs[kk][tx * 4];
            float a0 = As[ty * 2 + 0][kk];
            float a1 = As[ty * 2 + 1][kk];
            acc0.x += a0 * bv.x; acc0.y += a0 * bv.y;
            acc0.z += a0 * bv.z; acc0.w += a0 * bv.w;
            acc1.x += a1 * bv.x; acc1.y += a1 * bv.y;
            acc1.z += a1 * bv.z; acc1.w += a1 * bv.w;
        }
        __syncthreads();
    }

    float4 bb = *(const float4*)&bias[tx * 4];
    float e00 = eclamp(acc0.x + bb.x), e01 = eclamp(acc0.y + bb.y);
    float e02 = eclamp(acc0.z + bb.z), e03 = eclamp(acc0.w + bb.w);
    float e10 = eclamp(acc1.x + bb.x), e11 = eclamp(acc1.y + bb.y);
    float e12 = eclamp(acc1.z + bb.z), e13 = eclamp(acc1.w + bb.w);

    const int r0 = row0 + ty * 2;
    if (isE) {
        float4* d0 = (float4*)(g_Et2 + (size_t)(r0 + 0) * NU + 4 * tx);
        d0[0] = make_float4(e00, e00, e01, e01);
        d0[1] = make_float4(e02, e02, e03, e03);
        float4* d1 = (float4*)(g_Et2 + (size_t)(r0 + 1) * NU + 4 * tx);
        d1[0] = make_float4(e10, e10, e11, e11);
        d1[1] = make_float4(e12, e12, e13, e13);
    } else {
        int b0 = r0 >> 7;
        int k0 = r0 & 127;
        float* dst = &g_EkT[b0 * NU * NK];
        dst[(4 * tx + 0) * NK + k0] = e00;
        dst[(4 * tx + 1) * NK + k0] = e01;
        dst[(4 * tx + 2) * NK + k0] = e02;
        dst[(4 * tx + 3) * NK + k0] = e03;
        dst[(4 * tx + 0) * NK + k0 + 1] = e10;
        dst[(4 * tx + 1) * NK + k0 + 1] = e11;
        dst[(4 * tx + 2) * NK + k0 + 1] = e12;
        dst[(4 * tx + 3) * NK + k0 + 1] = e13;
    }
}

// ---------------------------------------------------------------------------
// Fused score + softmax + context — now 512 threads (16 warps, 4/SMSP) to
// fill the issue holes of the rcp(lat16)->fma chains. Warp w owns
// t = {2w, 2w+1} in every phase; lane owns k = 4*lane..+3.
// score[t,k] (up to softmax-invariant const) = sum_u -2*V_u / (1 + Et*Ek),
// two u-terms share one rcp:  V0/q0 + V1/q1 = (V0*q1 + V1*q0) / (q0*q1).
// smem (230400 B, 1 CTA/SM):
//   know[128][256] 128KB | EkT[128][128] 64KB |
//   Et2[32][128] float2 32KB (warp-private rows; reused as duplicated attn) |
//   v2 1KB
// ---------------------------------------------------------------------------
__global__ __launch_bounds__(512) void fused_kernel(
    const float* __restrict__ knw, const float* __restrict__ V,
    float* __restrict__ out)
{
    extern __shared__ float smem[];
    float*  know_s = smem;                          // 32768 floats
    float*  EkT_s  = smem + NK * ND;                // 16384 floats
    float2* Et2_s  = (float2*)(EkT_s + NU * NK);    // 4096 float2
    float2* v2_s   = Et2_s + 32 * NU;               // 128 float2

    const int b    = blockIdx.y;
    const int t0   = blockIdx.x * 32;
    const int tid  = threadIdx.x;
    const int lane = tid & 31;
    const int w    = tid >> 5;

    // ---- stage (float4, coalesced, 512 threads) ----
    {
        const float4* s = (const float4*)(knw + b * NK * ND);
        float4* d = (float4*)know_s;
        #pragma unroll
        for (int i = 0; i < 16; i++) d[tid + i * 512] = s[tid + i * 512];
    }
    {
        const float4* s = (const float4*)(g_EkT + b * NU * NK);
        float4* d = (float4*)EkT_s;
        #pragma unroll
        for (int i = 0; i < 8; i++) d[tid + i * 512] = s[tid + i * 512];
    }
    {
        const float4* s = (const float4*)(g_Et2 + (size_t)(b * NT + t0) * NU);
        float4* d = (float4*)Et2_s;
        #pragma unroll
        for (int i = 0; i < 4; i++) d[tid + i * 512] = s[tid + i * 512];
    }
    if (tid < NU) {
        float vv = -2.0f * V[tid];
        v2_s[tid] = make_float2(vv, vv);
    }
    __syncthreads();   // the ONLY block-wide sync

    const int lt0 = 2 * w;   // first local t this warp owns

    // ---- score: acc[tt][0]=(k0,k1) packed, acc[tt][1]=(k2,k3) packed ----
    unsigned long long acc[2][2];
    acc[0][0] = 0ull; acc[0][1] = 0ull;
    acc[1][0] = 0ull; acc[1][1] = 0ull;

    #pragma unroll 4
    for (int u = 0; u < NU; u += 2) {
        ulonglong2 ek0 = ((const ulonglong2*)&EkT_s[(u + 0) * NK])[lane];
        ulonglong2 ek1 = ((const ulonglong2*)&EkT_s[(u + 1) * NK])[lane];
        unsigned long long v0 = *(const unsigned long long*)&v2_s[u + 0];
        unsigned long long v1 = *(const unsigned long long*)&v2_s[u + 1];
        #pragma unroll
        for (int tt = 0; tt < 2; tt++) {
            unsigned long long et0 =
                *(const unsigned long long*)&Et2_s[(lt0 + tt) * NU + u + 0];
            unsigned long long et1 =
                *(const unsigned long long*)&Et2_s[(lt0 + tt) * NU + u + 1];
            // k-slots (0,1)
            unsigned long long q0 = fma2(et0, ek0.x, ONE2);
            unsigned long long q1 = fma2(et1, ek1.x, ONE2);
            unsigned long long num = fma2(v0, q1, mul2(v1, q0));
            acc[tt][0] = fma2(num, rcp2(mul2(q0, q1)), acc[tt][0]);
            // k-slots (2,3)
            q0 = fma2(et0, ek0.y, ONE2);
            q1 = fma2(et1, ek1.y, ONE2);
            num = fma2(v0, q1, mul2(v1, q0));
            acc[tt][1] = fma2(num, rcp2(mul2(q0, q1)), acc[tt][1]);
        }
    }

    // ---- softmax over K (in-warp); constants cancel ----
    #pragma unroll
    for (int tt = 0; tt < 2; tt++) {
        float2 axy = u2f(acc[tt][0]);
        float2 azw = u2f(acc[tt][1]);
        float4 sv = make_float4(axy.x, axy.y, azw.x, azw.y);
        float m = fmaxf(fmaxf(sv.x, sv.y), fmaxf(sv.z, sv.w));
        #pragma unroll
        for (int o = 16; o > 0; o >>= 1)
            m = fmaxf(m, __shfl_xor_sync(0xffffffffu, m, o));
        float4 p;
        p.x = __expf(sv.x - m);
        p.y = __expf(sv.y - m);
        p.z = __expf(sv.z - m);
        p.w = __expf(sv.w - m);
        float sum = (p.x + p.y) + (p.z + p.w);
        #pragma unroll
        for (int o = 16; o > 0; o >>= 1)
            sum += __shfl_xor_sync(0xffffffffu, sum, o);
        float inv = __fdividef(1.0f, sum);
        p.x *= inv; p.y *= inv; p.z *= inv; p.w *= inv;
        // overwrite OWN Et2 row with duplicated attn (p,p); row = 128 float2
        float2* arow = Et2_s + (lt0 + tt) * NU;
        arow[4 * lane + 0] = make_float2(p.x, p.x);
        arow[4 * lane + 1] = make_float2(p.y, p.y);
        arow[4 * lane + 2] = make_float2(p.z, p.z);
        arow[4 * lane + 3] = make_float2(p.w, p.w);
    }
    __syncwarp();

    // ---- context (FFMA2): out[t][d] = sum_k attn[t][k] * know[k][d] ----
    unsigned long long c[2][4];
    #pragma unroll
    for (int i = 0; i < 2; i++)
        #pragma unroll
        for (int j = 0; j < 4; j++) c[i][j] = 0ull;

    #pragma unroll 4
    for (int k = 0; k < NK; k++) {
        const float* row = &know_s[k * ND];
        ulonglong2 lo = ((const ulonglong2*)row)[lane];        // d=4*lane..+3
        ulonglong2 hi = ((const ulonglong2*)row)[lane + 32];   // d=128+4*lane..+3
        #pragma unroll
        for (int tt = 0; tt < 2; tt++) {
            unsigned long long a =
                *(const unsigned long long*)&Et2_s[(lt0 + tt) * NU + k];
            c[tt][0] = fma2(a, lo.x, c[tt][0]);
            c[tt][1] = fma2(a, lo.y, c[tt][1]);
            c[tt][2] = fma2(a, hi.x, c[tt][2]);
            c[tt][3] = fma2(a, hi.y, c[tt][3]);
        }
    }

    #pragma unroll
    for (int tt = 0; tt < 2; tt++) {
        float* o = out + (size_t)(b * NT + t0 + lt0 + tt) * ND;
        ((ulonglong2*)o)[lane]      = make_ulonglong2(c[tt][0], c[tt][1]);
        ((ulonglong2*)o)[lane + 32] = make_ulonglong2(c[tt][2], c[tt][3]);
    }
}

// ---------------------------------------------------------------------------
// Launch
// ---------------------------------------------------------------------------
extern "C" void kernel_launch(void* const* d_in, const int* in_sizes, int n_in,
                              void* d_out, int out_size)
{
    const float* knw = (const float*)d_in[0];   // knowledge_onehot [16,128,256]
    const float* enc = (const float*)d_in[1];   // encoder_outputs  [16,256,256]
    const float* W1  = (const float*)d_in[2];
    const float* b1  = (const float*)d_in[3];
    const float* W2  = (const float*)d_in[4];
    const float* b2  = (const float*)d_in[5];
    const float* V   = (const float*)d_in[6];
    // d_in[7] = bV: cancels in softmax. Unused.

    if (n_in >= 2 && in_sizes[0] == NB * NT * ND && in_sizes[1] == NB * NK * ND) {
        const float* tmp = knw; knw = enc; enc = tmp;
    }

    // 32768 + 16384 + 8192 + 256 floats = 230400 bytes
    const int smem_bytes = (NK * ND + NU * NK + 32 * NU * 2 + NU * 2) * (int)sizeof(float);
    cudaFuncSetAttribute(fused_kernel, cudaFuncAttributeMaxDynamicSharedMemorySize,
                         smem_bytes);

    proj_kernel<<<384, 256>>>(enc, knw, W1, b1, W2, b2);

    dim3 grid(NT / 32, NB);
    fused_kernel<<<grid, 512, smem_bytes>>>(knw, V, (float*)d_out);

    (void)n_in; (void)out_size;
}

// round 15
// speedup vs baseline: 1.1134x; 1.1134x over previous
#include <cuda_runtime.h>

// Problem constants
#define NB 16
#define NT 256
#define NK 128
#define ND 256   // D_E == D_K == 256
#define NU 128

// Scratch (allocation-free rule: __device__ globals)
__device__ float2 g_Et2[NB * NT * NU];   // [b*NT+t][u] : (exp(2e), exp(2e)) duplicated
__device__ float  g_EkT[NB * NU * NK];   // [b][u][k]   : exp(2kp), transposed

// exp(clamp(2x)) — tanh(a+b) = 1 - 2/(1 + e^{2a}e^{2b}).
// Clamp +-10 so a product of FOUR q-terms (q <= 1+e^20) stays < FLT_MAX.
__device__ __forceinline__ float eclamp(float x) {
    return __expf(fminf(fmaxf(2.0f * x, -10.0f), 10.0f));
}

// Packed f32x2 ops (sm_100+)
__device__ __forceinline__ unsigned long long fma2(unsigned long long a,
                                                   unsigned long long b,
                                                   unsigned long long c) {
    unsigned long long d;
    asm("fma.rn.f32x2 %0, %1, %2, %3;" : "=l"(d) : "l"(a), "l"(b), "l"(c));
    return d;
}
__device__ __forceinline__ unsigned long long mul2(unsigned long long a,
                                                   unsigned long long b) {
    unsigned long long d;
    asm("mul.rn.f32x2 %0, %1, %2;" : "=l"(d) : "l"(a), "l"(b));
    return d;
}
__device__ __forceinline__ unsigned long long add2(unsigned long long a,
                                                   unsigned long long b) {
    unsigned long long d;
    asm("add.rn.f32x2 %0, %1, %2;" : "=l"(d) : "l"(a), "l"(b));
    return d;
}
// packed reciprocal: 2x rcp.approx
__device__ __forceinline__ unsigned long long rcp2(unsigned long long v) {
    unsigned long long r;
    asm("{\n\t"
        ".reg .f32 lo, hi, rl, rh;\n\t"
        "mov.b64 {lo, hi}, %1;\n\t"
        "rcp.approx.f32 rl, lo;\n\t"
        "rcp.approx.f32 rh, hi;\n\t"
        "mov.b64 %0, {rl, rh};\n\t"
        "}" : "=l"(r) : "l"(v));
    return r;
}
__device__ __forceinline__ float2 u2f(unsigned long long v) {
    float2 r;
    asm("mov.b64 {%0, %1}, %2;" : "=f"(r.x), "=f"(r.y) : "l"(v));
    return r;
}

#define ONE2 0x3F8000003F800000ull   // packed (1.0f, 1.0f)

// ---------------------------------------------------------------------------
// Projection kernel, re-blocked: 32 rows x 128 cols per block, 256 threads,
// each warp owns 4 rows (A value is a warp-broadcast LDS.128 from a
// transposed A-tile), each thread 4x4 outputs -> 2 LDS per 16 FFMA.
//   blocks [0,128):   Et = exp(2*(enc@W1+b1))  -> g_Et2 duplicated
//   blocks [128,192): Ek = exp(2*(knw@W2+b2))  -> g_EkT transposed
// ---------------------------------------------------------------------------
__global__ __launch_bounds__(256) void proj_kernel(
    const float* __restrict__ enc, const float* __restrict__ knw,
    const float* __restrict__ W1, const float* __restrict__ b1,
    const float* __restrict__ W2, const float* __restrict__ b2)
{
    const int blk = blockIdx.x;
    const bool isE = (blk < 128);
    const float* __restrict__ A    = isE ? enc : knw;
    const float* __restrict__ W    = isE ? W1  : W2;
    const float* __restrict__ bias = isE ? b1  : b2;
    const int row0 = (isE ? blk : (blk - 128)) * 32;

    __shared__ float AsT[32][32];   // [kk][row]  (transposed A tile)
    __shared__ float Bs[32][128];

    const int tid = threadIdx.x;
    const int tx  = tid & 31;   // lane -> 4 output cols (4*tx..)
    const int w   = tid >> 5;   // warp -> 4 output rows (4*w..)

    float4 acc[4];
    #pragma unroll
    for (int i = 0; i < 4; i++) acc[i] = make_float4(0.f, 0.f, 0.f, 0.f);

    for (int kc = 0; kc < ND; kc += 32) {
        // A tile, stored transposed: thread (r = tid&31, c4 = tid>>5)
        {
            int r  = tid & 31;
            int c4 = tid >> 5;   // 0..7
            float4 a = *(const float4*)&A[(row0 + r) * ND + kc + c4 * 4];
            AsT[4 * c4 + 0][r] = a.x;
            AsT[4 * c4 + 1][r] = a.y;
            AsT[4 * c4 + 2][r] = a.z;
            AsT[4 * c4 + 3][r] = a.w;
        }
        // B tile: 1024 float4, 4 per thread
        #pragma unroll
        for (int i = 0; i < 4; i++) {
            int lin = tid + i * 256;
            int r   = lin >> 5;
            int c4  = lin & 31;
            *(float4*)&Bs[r][c4 * 4] = *(const float4*)&W[(kc + r) * NU + c4 * 4];
        }
        __syncthreads();

        #pragma unroll
        for (int kk = 0; kk < 32; kk++) {
            float4 bv = *(const float4*)&Bs[kk][tx * 4];
            float4 av = *(const float4*)&AsT[kk][4 * w];   // warp-broadcast
            acc[0].x += av.x * bv.x; acc[0].y += av.x * bv.y;
            acc[0].z += av.x * bv.z; acc[0].w += av.x * bv.w;
            acc[1].x += av.y * bv.x; acc[1].y += av.y * bv.y;
            acc[1].z += av.y * bv.z; acc[1].w += av.y * bv.w;
            acc[2].x += av.z * bv.x; acc[2].y += av.z * bv.y;
            acc[2].z += av.z * bv.z; acc[2].w += av.z * bv.w;
            acc[3].x += av.w * bv.x; acc[3].y += av.w * bv.y;
            acc[3].z += av.w * bv.z; acc[3].w += av.w * bv.w;
        }
        __syncthreads();
    }

    float4 bb = *(const float4*)&bias[tx * 4];
    #pragma unroll
    for (int i = 0; i < 4; i++) {
        float e0 = eclamp(acc[i].x + bb.x);
        float e1 = eclamp(acc[i].y + bb.y);
        float e2 = eclamp(acc[i].z + bb.z);
        float e3 = eclamp(acc[i].w + bb.w);
        const int r0 = row0 + 4 * w + i;
        if (isE) {
            float4* d = (float4*)(g_Et2 + (size_t)r0 * NU + 4 * tx);
            d[0] = make_float4(e0, e0, e1, e1);
            d[1] = make_float4(e2, e2, e3, e3);
        } else {
            int b0 = r0 >> 7;
            int k0 = r0 & 127;
            float* dst = &g_EkT[b0 * NU * NK];
            dst[(4 * tx + 0) * NK + k0] = e0;
            dst[(4 * tx + 1) * NK + k0] = e1;
            dst[(4 * tx + 2) * NK + k0] = e2;
            dst[(4 * tx + 3) * NK + k0] = e3;
        }
    }
}

// ---------------------------------------------------------------------------
// Fused score + softmax + context. 512 threads (16 warps), grid (NT/32, NB).
//  score:   warp w owns t = {2w, 2w+1}, lane owns k = 4*lane..+3.
//           u-QUAD shares one rcp2:
//           sum_j Vj/qj = [(V0q1+V1q0)p23 + (V2q3+V3q2)p01] / (p01*p23)
//  softmax: in-warp (score owner), writes duplicated attn over Et2 rows.
//  context: warp w owns t-quad (w&7) and k-half (w>>3); know traffic halves.
//           Partials reduced through the retired EkT region.
// smem (230400 B, 1 CTA/SM):
//   know[128][256] 128KB | EkT[128][128] 64KB (-> red[2][32][256]) |
//   Et2[32][128] float2 32KB (-> duplicated attn) | v2 1KB
// ---------------------------------------------------------------------------
__global__ __launch_bounds__(512) void fused_kernel(
    const float* __restrict__ knw, const float* __restrict__ V,
    float* __restrict__ out)
{
    extern __shared__ float smem[];
    float*  know_s = smem;                          // 32768 floats
    float*  EkT_s  = smem + NK * ND;                // 16384 floats (-> red)
    float2* Et2_s  = (float2*)(EkT_s + NU * NK);    // 4096 float2 (-> attn2)
    float2* v2_s   = Et2_s + 32 * NU;               // 128 float2
    float*  red    = EkT_s;                         // [2][32][256] partials

    const int b    = blockIdx.y;
    const int t0   = blockIdx.x * 32;
    const int tid  = threadIdx.x;
    const int lane = tid & 31;
    const int w    = tid >> 5;

    // ---- stage (float4, coalesced, 512 threads) ----
    {
        const float4* s = (const float4*)(knw + b * NK * ND);
        float4* d = (float4*)know_s;
        #pragma unroll
        for (int i = 0; i < 16; i++) d[tid + i * 512] = s[tid + i * 512];
    }
    {
        const float4* s = (const float4*)(g_EkT + b * NU * NK);
        float4* d = (float4*)EkT_s;
        #pragma unroll
        for (int i = 0; i < 8; i++) d[tid + i * 512] = s[tid + i * 512];
    }
    {
        const float4* s = (const float4*)(g_Et2 + (size_t)(b * NT + t0) * NU);
        float4* d = (float4*)Et2_s;
        #pragma unroll
        for (int i = 0; i < 4; i++) d[tid + i * 512] = s[tid + i * 512];
    }
    if (tid < NU) {
        float vv = -2.0f * V[tid];
        v2_s[tid] = make_float2(vv, vv);
    }
    __syncthreads();

    const int lt0 = 2 * w;   // score/softmax/output rows this warp owns

    // ---- score: acc[tt][0]=(k0,k1), acc[tt][1]=(k2,k3), u-quad rcp sharing --
    unsigned long long acc[2][2];
    acc[0][0] = 0ull; acc[0][1] = 0ull;
    acc[1][0] = 0ull; acc[1][1] = 0ull;

    #pragma unroll 2
    for (int u = 0; u < NU; u += 4) {
        ulonglong2 ek0 = ((const ulonglong2*)&EkT_s[(u + 0) * NK])[lane];
        ulonglong2 ek1 = ((const ulonglong2*)&EkT_s[(u + 1) * NK])[lane];
        ulonglong2 ek2 = ((const ulonglong2*)&EkT_s[(u + 2) * NK])[lane];
        ulonglong2 ek3 = ((const ulonglong2*)&EkT_s[(u + 3) * NK])[lane];
        unsigned long long v0 = *(const unsigned long long*)&v2_s[u + 0];
        unsigned long long v1 = *(const unsigned long long*)&v2_s[u + 1];
        unsigned long long v2 = *(const unsigned long long*)&v2_s[u + 2];
        unsigned long long v3 = *(const unsigned long long*)&v2_s[u + 3];
        #pragma unroll
        for (int tt = 0; tt < 2; tt++) {
            const float2* erow = Et2_s + (lt0 + tt) * NU;
            unsigned long long et0 = *(const unsigned long long*)&erow[u + 0];
            unsigned long long et1 = *(const unsigned long long*)&erow[u + 1];
            unsigned long long et2 = *(const unsigned long long*)&erow[u + 2];
            unsigned long long et3 = *(const unsigned long long*)&erow[u + 3];
            #pragma unroll
            for (int slot = 0; slot < 2; slot++) {
                unsigned long long e0 = slot ? ek0.y : ek0.x;
                unsigned long long e1 = slot ? ek1.y : ek1.x;
                unsigned long long e2 = slot ? ek2.y : ek2.x;
                unsigned long long e3 = slot ? ek3.y : ek3.x;
                unsigned long long q0 = fma2(et0, e0, ONE2);
                unsigned long long q1 = fma2(et1, e1, ONE2);
                unsigned long long q2 = fma2(et2, e2, ONE2);
                unsigned long long q3 = fma2(et3, e3, ONE2);
                unsigned long long p01 = mul2(q0, q1);
                unsigned long long p23 = mul2(q2, q3);
                unsigned long long r   = rcp2(mul2(p01, p23));
                unsigned long long t01 = fma2(v0, q1, mul2(v1, q0));
                unsigned long long t23 = fma2(v2, q3, mul2(v3, q2));
                unsigned long long num = fma2(t01, p23, mul2(t23, p01));
                acc[tt][slot] = fma2(num, r, acc[tt][slot]);
            }
        }
    }

    // ---- softmax over K (in-warp); constants cancel ----
    #pragma unroll
    for (int tt = 0; tt < 2; tt++) {
        float2 axy = u2f(acc[tt][0]);
        float2 azw = u2f(acc[tt][1]);
        float4 sv = make_float4(axy.x, axy.y, azw.x, azw.y);
        float m = fmaxf(fmaxf(sv.x, sv.y), fmaxf(sv.z, sv.w));
        #pragma unroll
        for (int o = 16; o > 0; o >>= 1)
            m = fmaxf(m, __shfl_xor_sync(0xffffffffu, m, o));
        float4 p;
        p.x = __expf(sv.x - m);
        p.y = __expf(sv.y - m);
        p.z = __expf(sv.z - m);
        p.w = __expf(sv.w - m);
        float sum = (p.x + p.y) + (p.z + p.w);
        #pragma unroll
        for (int o = 16; o > 0; o >>= 1)
            sum += __shfl_xor_sync(0xffffffffu, sum, o);
        float inv = __fdividef(1.0f, sum);
        p.x *= inv; p.y *= inv; p.z *= inv; p.w *= inv;
        float2* arow = Et2_s + (lt0 + tt) * NU;   // overwrite OWN Et2 row
        arow[4 * lane + 0] = make_float2(p.x, p.x);
        arow[4 * lane + 1] = make_float2(p.y, p.y);
        arow[4 * lane + 2] = make_float2(p.z, p.z);
        arow[4 * lane + 3] = make_float2(p.w, p.w);
    }
    __syncthreads();   // attn visible; all EkT reads done (region -> red)

    // ---- context: warp w -> t-quad (w&7), k-half (w>>3) ----
    const int tq = w & 7;
    const int kh = (w >> 3) * 64;
    {
        unsigned long long c[4][4];
        #pragma unroll
        for (int i = 0; i < 4; i++)
            #pragma unroll
            for (int j = 0; j < 4; j++) c[i][j] = 0ull;

        #pragma unroll 4
        for (int kk = 0; kk < 64; kk++) {
            const int k = kh + kk;
            const float* row = &know_s[k * ND];
            ulonglong2 lo = ((const ulonglong2*)row)[lane];        // d=4l..+3
            ulonglong2 hi = ((const ulonglong2*)row)[lane + 32];   // d=128+4l..
            #pragma unroll
            for (int tt = 0; tt < 4; tt++) {
                unsigned long long a =
                    *(const unsigned long long*)&Et2_s[(4 * tq + tt) * NU + k];
                c[tt][0] = fma2(a, lo.x, c[tt][0]);
                c[tt][1] = fma2(a, lo.y, c[tt][1]);
                c[tt][2] = fma2(a, hi.x, c[tt][2]);
                c[tt][3] = fma2(a, hi.y, c[tt][3]);
            }
        }

        // store partials: red[h][lt][d]
        const int base = (w >> 3) * 32 * ND;
        #pragma unroll
        for (int tt = 0; tt < 4; tt++) {
            float* r = &red[base + (4 * tq + tt) * ND];
            ((ulonglong2*)r)[lane]         = make_ulonglong2(c[tt][0], c[tt][1]);
            ((ulonglong2*)(r + 128))[lane] = make_ulonglong2(c[tt][2], c[tt][3]);
        }
    }
    __syncthreads();

    // ---- reduce halves + write out: warp w handles t = {2w, 2w+1} ----
    #pragma unroll
    for (int tt = 0; tt < 2; tt++) {
        const int lt = lt0 + tt;
        const ulonglong2* p0 = (const ulonglong2*)&red[lt * ND];
        const ulonglong2* p1 = (const ulonglong2*)&red[32 * ND + lt * ND];
        float* o = out + (size_t)(b * NT + t0 + lt) * ND;
        #pragma unroll
        for (int half = 0; half < 2; half++) {
            ulonglong2 x = p0[lane + half * 32];
            ulonglong2 y = p1[lane + half * 32];
            ((ulonglong2*)o)[lane + half * 32] =
                make_ulonglong2(add2(x.x, y.x), add2(x.y, y.y));
        }
    }
}

// ---------------------------------------------------------------------------
// Launch
// ---------------------------------------------------------------------------
extern "C" void kernel_launch(void* const* d_in, const int* in_sizes, int n_in,
                              void* d_out, int out_size)
{
    const float* knw = (const float*)d_in[0];   // knowledge_onehot [16,128,256]
    const float* enc = (const float*)d_in[1];   // encoder_outputs  [16,256,256]
    const float* W1  = (const float*)d_in[2];
    const float* b1  = (const float*)d_in[3];
    const float* W2  = (const float*)d_in[4];
    const float* b2  = (const float*)d_in[5];
    const float* V   = (const float*)d_in[6];
    // d_in[7] = bV: cancels in softmax. Unused.

    if (n_in >= 2 && in_sizes[0] == NB * NT * ND && in_sizes[1] == NB * NK * ND) {
        const float* tmp = knw; knw = enc; enc = tmp;
    }

    // 32768 + 16384 + 8192 + 256 floats = 230400 bytes
    const int smem_bytes = (NK * ND + NU * NK + 32 * NU * 2 + NU * 2) * (int)sizeof(float);
    cudaFuncSetAttribute(fused_kernel, cudaFuncAttributeMaxDynamicSharedMemorySize,
                         smem_bytes);

    proj_kernel<<<192, 256>>>(enc, knw, W1, b1, W2, b2);

    dim3 grid(NT / 32, NB);
    fused_kernel<<<grid, 512, smem_bytes>>>(knw, V, (float*)d_out);

    (void)n_in; (void)out_size;
}